// round 17
// baseline (speedup 1.0000x reference)
#include <cuda_runtime.h>

#define IMG    512
#define SW     32
#define SH     256
#define NCH    8
#define BROWS  42          // hh rows (32 new + 10 carry)
#define SROWS  32          // spst rows
#define ICOLS  42
#define NBLK   1024        // 16 * 2 * 32

#define C1 1.0e-4f
#define C2 9.0e-4f

// Gaussian(sigma=1.5,k=11) literals (~1e-7 vs runtime fp32; tol 1e-3)
#define WLIT(k) ((k)==0 ? 0.00102838f : (k)==1 ? 0.00759876f : (k)==2 ? 0.03600077f : \
                 (k)==3 ? 0.10936069f : (k)==4 ? 0.21300554f : (k)==5 ? 0.26601172f : \
                 (k)==6 ? 0.21300554f : (k)==7 ? 0.10936069f : (k)==8 ? 0.03600077f : \
                 (k)==9 ? 0.00759876f : 0.00102838f)
#define W2X(k) ((k) <= 5 ? (k) : 10 - (k))   // symmetric window

typedef unsigned long long ull;
typedef unsigned int       u32;
typedef unsigned short     u16;

__device__ __forceinline__ ull d_pack2(float lo, float hi) {
    ull r; asm("mov.b64 %0, {%1, %2};" : "=l"(r) : "f"(lo), "f"(hi)); return r;
}
__device__ __forceinline__ void d_unpack2(ull v, float& lo, float& hi) {
    asm("mov.b64 {%0, %1}, %2;" : "=f"(lo), "=f"(hi) : "l"(v));
}
// pack two f32 -> bf16x2 word (upper = hi, lower = lo)
__device__ __forceinline__ u32 d_bf2(float hi, float lo) {
    u32 r; asm("cvt.rn.bf16x2.f32 %0, %1, %2;" : "=r"(r) : "f"(hi), "f"(lo)); return r;
}
// bf16x2 word -> f32x2 pair {lo, hi}
__device__ __forceinline__ ull d_bfup(u32 v) {
    float lo = __uint_as_float(v << 16);
    float hi = __uint_as_float(v & 0xFFFF0000u);
    return d_pack2(lo, hi);
}
#define FMA2(acc, a, b) asm("fma.rn.f32x2 %0, %1, %2, %0;" : "+l"(acc) : "l"(a), "l"(b))
#define MUL2(d, a, b)   asm("mul.rn.f32x2 %0, %1, %2;"      : "=l"(d)  : "l"(a), "l"(b))

__device__ float        g_partial[NBLK];
__device__ unsigned int g_count = 0;

__global__ __launch_bounds__(256, 5) void ssim_strip_kernel(
    const float* __restrict__ pred,
    const float* __restrict__ target,
    float* __restrict__ out)
{
    __shared__ __align__(16) u32 spst[SROWS][ICOLS];  // bf16x2 (lo=sig(p), hi=t)
    __shared__ __align__(16) u32 hh01[BROWS][32];     // bf16x2 (lo=Hp,  hi=Ht)
    __shared__ __align__(16) u32 hh23[BROWS][32];     // bf16x2 (lo=Hp2, hi=Ht2)
    __shared__ __align__(16) u16 hh4 [BROWS][32];     // bf16 Hpt
    __shared__ float wsum[8];
    __shared__ int   s_last;

    const int tid = threadIdx.x;

    const float* __restrict__ pimg = pred   + (size_t)blockIdx.z * IMG * IMG;
    const float* __restrict__ timg = target + (size_t)blockIdx.z * IMG * IMG;
    const int c0 = blockIdx.x * SW;
    const int r0 = blockIdx.y * SH;

    // decompositions
    const int lrow = tid >> 3;          // 0..31 load row
    const int lcol = tid & 7;           // 0..7  load col phase
    const int hr2  = tid >> 4;          // 0..15 H-pass row within pass
    const int hc2  = (tid & 15) * 2;    // 0..30 H-pass output col base (even)
    const int vj   = tid & 31;          // V-pass col
    const int vi0  = (tid >> 5) * 4;    // V-pass row base

    // packed weights: 6 unique (symmetric), in regs
    ull w2[6];
    #pragma unroll
    for (int k = 0; k < 6; k++) w2[k] = d_pack2(WLIT(k), WLIT(k));

    float local = 0.f;

#define LOAD_ROWS(GR_EXPR, DSTROW, ROWPRED)                                     \
    {                                                                           \
        const int gr = (GR_EXPR);                                               \
        const bool rok = (ROWPRED);                                             \
        const float* __restrict__ prow = pimg + gr * IMG;                       \
        const float* __restrict__ trow = timg + gr * IMG;                       \
        _Pragma("unroll")                                                       \
        for (int s = 0; s < 6; s++) {                                           \
            const int cc = lcol + 8 * s;                                        \
            if (cc < ICOLS) {                                                   \
                const int gc = c0 - 5 + cc;                                     \
                float pv = 0.f, tv = 0.f;                                       \
                if (rok && (unsigned)gc < IMG) {                                \
                    float x = prow[gc];                                         \
                    pv = 1.f / (1.f + __expf(-x));                              \
                    tv = trow[gc];                                              \
                }                                                               \
                spst[(DSTROW)][cc] = d_bf2(tv, pv);                             \
            }                                                                   \
        }                                                                       \
    }

#define HP_TAP(K, W)                                                            \
    {                                                                           \
        const float pa = __uint_as_float((W) << 16);                            \
        const float pb = __uint_as_float((W) & 0xFFFF0000u);                    \
        ull ab = d_pack2(pa, pb);                                               \
        ull abab; MUL2(abab, ab, ab);                                           \
        const float pab = pa * pb;                                              \
        if ((K) <= 10) {                                                        \
            FMA2(a01_0, w2[W2X(K)], ab); FMA2(a23_0, w2[W2X(K)], abab);         \
            a4_0 = fmaf(WLIT(K), pab, a4_0);                                    \
        }                                                                       \
        if ((K) >= 1) {                                                         \
            FMA2(a01_1, w2[W2X((K)-1)], ab); FMA2(a23_1, w2[W2X((K)-1)], abab); \
            a4_1 = fmaf(WLIT((K)-1), pab, a4_1);                                \
        }                                                                       \
    }

#define HPASS2(SRCROW, DSTROW)                                                  \
    {                                                                           \
        ull a01_0 = 0ull, a01_1 = 0ull, a23_0 = 0ull, a23_1 = 0ull;             \
        float a4_0 = 0.f, a4_1 = 0.f;                                           \
        _Pragma("unroll")                                                       \
        for (int kk = 0; kk < 6; kk++) {                                        \
            const uint2 q = *reinterpret_cast<const uint2*>(                    \
                                &spst[(SRCROW)][hc2 + 2 * kk]);                 \
            HP_TAP(2 * kk,     q.x);                                            \
            HP_TAP(2 * kk + 1, q.y);                                            \
        }                                                                       \
        float m0p, m0t, m1p, m1t;                                               \
        d_unpack2(a01_0, m0p, m0t);                                             \
        d_unpack2(a01_1, m1p, m1t);                                             \
        *reinterpret_cast<uint2*>(&hh01[(DSTROW)][hc2]) =                       \
            make_uint2(d_bf2(m0t, m0p), d_bf2(m1t, m1p));                       \
        d_unpack2(a23_0, m0p, m0t);                                             \
        d_unpack2(a23_1, m1p, m1t);                                             \
        *reinterpret_cast<uint2*>(&hh23[(DSTROW)][hc2]) =                       \
            make_uint2(d_bf2(m0t, m0p), d_bf2(m1t, m1p));                       \
        *reinterpret_cast<u32*>(&hh4[(DSTROW)][hc2]) = d_bf2(a4_1, a4_0);       \
    }

    // =================== prologue =====================
    LOAD_ROWS(r0 - 5 + lrow, lrow, ((unsigned)gr < IMG));   // rows -5..26
    __syncthreads();
    HPASS2(hr2,      hr2);          // hh rows 0..15
    HPASS2(hr2 + 16, hr2 + 16);     // hh rows 16..31
    __syncthreads();
    if (lrow < 10) LOAD_ROWS(r0 + 27 + lrow, lrow, true);   // rows 27..36
    __syncthreads();
    if (hr2 < 10) HPASS2(hr2, 32 + hr2);                    // hh rows 32..41
    __syncthreads();

    // =================== chunk loop =====================
    for (int ch = 0; ch < NCH; ch++) {
        // ---- V-pass + SSIM (bf16 loads, fp32 packed accumulation) ----
        {
            ull acc01[4], acc23[4];
            float acc4[4];
            #pragma unroll
            for (int u = 0; u < 4; u++) { acc01[u] = 0ull; acc23[u] = 0ull; acc4[u] = 0.f; }

            #pragma unroll
            for (int k = 0; k < 14; k++) {
                const ull v01 = d_bfup(hh01[vi0 + k][vj]);
                const ull v23 = d_bfup(hh23[vi0 + k][vj]);
                const float v4 = __uint_as_float(((u32)hh4[vi0 + k][vj]) << 16);
                #pragma unroll
                for (int u = 0; u < 4; u++) {
                    if (k - u >= 0 && k - u <= 10) {
                        FMA2(acc01[u], w2[W2X(k - u)], v01);
                        FMA2(acc23[u], w2[W2X(k - u)], v23);
                        acc4[u] = fmaf(WLIT(k - u), v4, acc4[u]);
                    }
                }
            }

            #pragma unroll
            for (int u = 0; u < 4; u++) {
                float mu1, mu2, bp, bt;
                d_unpack2(acc01[u], mu1, mu2);
                d_unpack2(acc23[u], bp, bt);
                const float mu1s = mu1 * mu1;
                const float mu2s = mu2 * mu2;
                const float mu12 = mu1 * mu2;
                const float sig1  = bp - mu1s;
                const float sig2  = bt - mu2s;
                const float sig12 = acc4[u] - mu12;
                const float num = (2.f * mu12 + C1) * (2.f * sig12 + C2);
                const float den = (mu1s + mu2s + C1) * (sig1 + sig2 + C2);
                local += 1.f - __fdividef(num, den);
            }
        }
        __syncthreads();

        if (ch < NCH - 1) {
            // ---- carry hh rows 32..41 -> 0..9 (float4; 200 tasks, 1/thread) ----
            {
                float4* f01 = reinterpret_cast<float4*>(hh01);  // 8 f4/row
                float4* f23 = reinterpret_cast<float4*>(hh23);  // 8 f4/row
                float4* f4p = reinterpret_cast<float4*>(hh4);   // 4 f4/row
                const int i = tid;
                if (i < 80)       f01[i]       = f01[256 + i];
                else if (i < 160) f23[i - 80]  = f23[256 + (i - 80)];
                else if (i < 200) f4p[i - 160] = f4p[128 + (i - 160)];
            }
            // ---- load next 32 input rows ----
            LOAD_ROWS(r0 + 32 * ch + 37 + lrow, lrow, (gr < IMG));
            __syncthreads();

            // ---- H-pass 32 new rows -> hh rows 10..41 ----
            HPASS2(hr2,      10 + hr2);
            HPASS2(hr2 + 16, 26 + hr2);
            __syncthreads();
        }
    }

    // ---- block reduction -> partial ----
    #pragma unroll
    for (int off = 16; off; off >>= 1)
        local += __shfl_down_sync(0xffffffffu, local, off);
    if ((tid & 31) == 0) wsum[tid >> 5] = local;
    __syncthreads();
    if (tid == 0) {
        float v = 0.f;
        #pragma unroll
        for (int i = 0; i < 8; i++) v += wsum[i];
        int blin = (blockIdx.z * 2 + blockIdx.y) * 16 + blockIdx.x;
        g_partial[blin] = v;
        __threadfence();
        unsigned old = atomicAdd(&g_count, 1u);
        s_last = (old == NBLK - 1) ? 1 : 0;
    }
    __syncthreads();

    // ---- last block: fixed-order final reduction ----
    if (s_last) {
        __threadfence();
        float s = g_partial[tid] + g_partial[tid + 256]
                + g_partial[tid + 512] + g_partial[tid + 768];
        #pragma unroll
        for (int off = 16; off; off >>= 1)
            s += __shfl_down_sync(0xffffffffu, s, off);
        if ((tid & 31) == 0) wsum[tid >> 5] = s;
        __syncthreads();
        if (tid == 0) {
            float v = 0.f;
            #pragma unroll
            for (int i = 0; i < 8; i++) v += wsum[i];
            out[0] = v * (1.0f / 8388608.0f);   // / (32*512*512)
            g_count = 0;                        // reset for next graph replay
        }
    }
}

extern "C" void kernel_launch(void* const* d_in, const int* in_sizes, int n_in,
                              void* d_out, int out_size)
{
    const float* pred   = (const float*)d_in[0];
    const float* target = (const float*)d_in[1];
    dim3 grid(16, 2, 32);
    ssim_strip_kernel<<<grid, 256>>>(pred, target, (float*)d_out);
}